// round 2
// baseline (speedup 1.0000x reference)
#include <cuda_runtime.h>
#include <math.h>

#define NEG_INF_F   (-9.0e15f)
#define LRELU_ALPHA (0.2f)

// ---------------------------------------------------------------------------
// Kernel A: masked edge-type attention + weighted aggregation.
// grid = (64 batches, 4 i-tiles), block = (128, 2) = 256 threads.
// ---------------------------------------------------------------------------
__global__ void __launch_bounds__(256) attn_kernel(
    const float* __restrict__ hidden,   // [64,128,128]
    const int*   __restrict__ adj,      // [64,128,128]
    const float* __restrict__ a,        // [128,4]
    float*       __restrict__ out)      // [64,128,128]
{
    extern __shared__ float smem[];
    float* h_t    = smem;               // 128*129  : h_t[d*129 + j] = hidden[b,j,d]
    float* a_s    = h_t + 128 * 129;    // 512
    float* attn_s = a_s + 512;          // 2*128
    float* red    = attn_s + 256;       // 2*4

    const int b   = blockIdx.x;
    const int tx  = threadIdx.x;        // 0..127  (j, then d)
    const int ty  = threadIdx.y;        // 0..1
    const int tid = ty * 128 + tx;

    const float* hb = hidden + b * 16384;
    #pragma unroll 8
    for (int idx = tid; idx < 16384; idx += 256) {
        int j = idx >> 7;
        int d = idx & 127;
        h_t[d * 129 + j] = hb[idx];     // coalesced global, conflict-free smem store
    }
    // 512 elements of a, 256 threads -> 2 each  (bug fixed from R1)
    a_s[tid]       = a[tid];
    a_s[tid + 256] = a[tid + 256];
    __syncthreads();

    const int lane = tx & 31;
    const int w    = tx >> 5;           // warp-in-group 0..3

    for (int ii = 0; ii < 16; ++ii) {
        const int i = blockIdx.y * 32 + ii * 2 + ty;

        // ---- alpha_j = selected edge-type score (or -9e15) ----
        const int e = adj[(b * 128 + i) * 128 + tx];
        float alpha = NEG_INF_F;
        if (e != 0) {
            const int k = e - 1;
            float acc = 0.f;
            #pragma unroll 8
            for (int d = 0; d < 128; ++d) {
                float hi = h_t[d * 129 + i];   // warp-broadcast
                float hj = h_t[d * 129 + tx];  // conflict-free
                float p  = hi * hj;
                float l  = fmaxf(p, 0.f) + LRELU_ALPHA * fminf(p, 0.f);
                acc = fmaf(l, a_s[d * 4 + k], acc);
            }
            alpha = acc;
        }

        // ---- softmax over j (128 threads sharing threadIdx.y) ----
        float m = alpha;
        #pragma unroll
        for (int o = 16; o; o >>= 1)
            m = fmaxf(m, __shfl_xor_sync(0xffffffffu, m, o));
        if (lane == 0) red[ty * 4 + w] = m;
        __syncthreads();
        m = fmaxf(fmaxf(red[ty * 4 + 0], red[ty * 4 + 1]),
                  fmaxf(red[ty * 4 + 2], red[ty * 4 + 3]));

        float ex = __expf(alpha - m);
        float s = ex;
        #pragma unroll
        for (int o = 16; o; o >>= 1)
            s += __shfl_xor_sync(0xffffffffu, s, o);
        __syncthreads();                 // all reads of red(max) done
        if (lane == 0) red[ty * 4 + w] = s;
        __syncthreads();
        s = (red[ty * 4 + 0] + red[ty * 4 + 1]) +
            (red[ty * 4 + 2] + red[ty * 4 + 3]);

        attn_s[ty * 128 + tx] = ex * (1.f / s);
        __syncthreads();

        // ---- output[b,i,d] = sum_j attn[j] * hidden[b,j,d]; thread owns d=tx ----
        float acc2 = 0.f;
        #pragma unroll 8
        for (int jj = 0; jj < 128; ++jj)
            acc2 = fmaf(attn_s[ty * 128 + jj], h_t[tx * 129 + jj], acc2);
        out[(b * 128 + i) * 128 + tx] = acc2;
        __syncthreads();                 // protect attn_s / red for next ii
    }
}

// ---------------------------------------------------------------------------
// Kernel B: attr_sess = A_attr_sess @ attr_embedding
// Flat SGEMM: C[8192,128] = A[8192,1000] * B[1000,128]
// BM=32, BN=128, BK=8; 256 threads; 4x4 register tile per thread.
// ---------------------------------------------------------------------------
__global__ void __launch_bounds__(256) attr_gemm_kernel(
    const float* __restrict__ A,   // [8192,1000]
    const float* __restrict__ B,   // [1000,128]
    float*       __restrict__ C)   // [8192,128]
{
    __shared__ float As[8][33];    // [kk][row], padded
    __shared__ float Bs[8][128];

    const int tid     = threadIdx.x;
    const int block_m = blockIdx.x * 32;
    const int ty      = tid >> 5;          // 0..7  -> rows ty*4 .. ty*4+3
    const int tx      = tid & 31;          // 0..31 -> cols tx*4 .. tx*4+3

    const int ar = tid >> 3;               // 0..31 row for A load
    const int ak = tid & 7;                // 0..7  k for A load
    const float* Aptr = A + (size_t)(block_m + ar) * 1000 + ak;

    float acc[4][4];
    #pragma unroll
    for (int r = 0; r < 4; ++r)
        #pragma unroll
        for (int c = 0; c < 4; ++c) acc[r][c] = 0.f;

    for (int k0 = 0; k0 < 1000; k0 += 8) {
        As[ak][ar] = Aptr[k0];
        #pragma unroll
        for (int t = 0; t < 4; ++t) {
            int idx = tid + t * 256;
            int kl  = idx >> 7;
            int c   = idx & 127;
            Bs[kl][c] = B[(size_t)(k0 + kl) * 128 + c];
        }
        __syncthreads();

        #pragma unroll
        for (int kk = 0; kk < 8; ++kk) {
            float4 bv = *(const float4*)&Bs[kk][tx * 4];
            float a0 = As[kk][ty * 4 + 0];
            float a1 = As[kk][ty * 4 + 1];
            float a2 = As[kk][ty * 4 + 2];
            float a3 = As[kk][ty * 4 + 3];
            acc[0][0] = fmaf(a0, bv.x, acc[0][0]);
            acc[0][1] = fmaf(a0, bv.y, acc[0][1]);
            acc[0][2] = fmaf(a0, bv.z, acc[0][2]);
            acc[0][3] = fmaf(a0, bv.w, acc[0][3]);
            acc[1][0] = fmaf(a1, bv.x, acc[1][0]);
            acc[1][1] = fmaf(a1, bv.y, acc[1][1]);
            acc[1][2] = fmaf(a1, bv.z, acc[1][2]);
            acc[1][3] = fmaf(a1, bv.w, acc[1][3]);
            acc[2][0] = fmaf(a2, bv.x, acc[2][0]);
            acc[2][1] = fmaf(a2, bv.y, acc[2][1]);
            acc[2][2] = fmaf(a2, bv.z, acc[2][2]);
            acc[2][3] = fmaf(a2, bv.w, acc[2][3]);
            acc[3][0] = fmaf(a3, bv.x, acc[3][0]);
            acc[3][1] = fmaf(a3, bv.y, acc[3][1]);
            acc[3][2] = fmaf(a3, bv.z, acc[3][2]);
            acc[3][3] = fmaf(a3, bv.w, acc[3][3]);
        }
        __syncthreads();
    }

    #pragma unroll
    for (int r = 0; r < 4; ++r) {
        int row = block_m + ty * 4 + r;
        float4 v = make_float4(acc[r][0], acc[r][1], acc[r][2], acc[r][3]);
        *(float4*)&C[(size_t)row * 128 + tx * 4] = v;
    }
}

// ---------------------------------------------------------------------------
extern "C" void kernel_launch(void* const* d_in, const int* in_sizes, int n_in,
                              void* d_out, int out_size)
{
    const float* hidden   = (const float*)d_in[0];  // [64,128,128]
    const int*   adj      = (const int*)  d_in[1];  // [64,128,128]
    const float* a        = (const float*)d_in[2];  // [128,4]
    const float* A_attr   = (const float*)d_in[3];  // [64,128,1000]
    const float* attr_emb = (const float*)d_in[4];  // [1000,128]

    float* out       = (float*)d_out;
    float* out_attn  = out;                  // output    [64,128,128]
    float* out_attr  = out + 64 * 128 * 128; // attr_sess [64,128,128]

    size_t smem = (size_t)(128 * 129 + 512 + 256 + 8) * sizeof(float);
    cudaFuncSetAttribute(attn_kernel,
                         cudaFuncAttributeMaxDynamicSharedMemorySize, (int)smem);

    attn_kernel<<<dim3(64, 4), dim3(128, 2), smem>>>(hidden, adj, a, out_attn);
    attr_gemm_kernel<<<256, 256>>>(A_attr, attr_emb, out_attr);
}

// round 7
// speedup vs baseline: 1.5211x; 1.5211x over previous
#include <cuda_runtime.h>
#include <cuda_bf16.h>
#include <cstdint>
#include <math.h>

#define NEG_INF_F   (-9.0e15f)
#define LRELU_ALPHA (0.2f)

extern __shared__ char dyn_smem[];

// ============================================================================
// Helpers
// ============================================================================
__device__ __forceinline__ uint32_t s2u(const void* p) {
    uint32_t a;
    asm("{ .reg .u64 t; cvta.to.shared.u64 t, %1; cvt.u32.u64 %0, t; }"
        : "=r"(a) : "l"(p));
    return a;
}
__device__ __forceinline__ uint32_t lds32(uint32_t addr) {
    uint32_t v;
    asm volatile("ld.shared.b32 %0, [%1];" : "=r"(v) : "r"(addr));
    return v;
}
__device__ __forceinline__ void mma16816(float* c, const uint32_t* a, const uint32_t* b) {
    asm volatile(
        "mma.sync.aligned.m16n8k16.row.col.f32.bf16.bf16.f32 "
        "{%0,%1,%2,%3}, {%4,%5,%6,%7}, {%8,%9}, {%0,%1,%2,%3};"
        : "+f"(c[0]), "+f"(c[1]), "+f"(c[2]), "+f"(c[3])
        : "r"(a[0]), "r"(a[1]), "r"(a[2]), "r"(a[3]), "r"(b[0]), "r"(b[1]));
}
__device__ __forceinline__ uint32_t pack_bf2(float a, float b) {
    __nv_bfloat162 t = __floats2bfloat162_rn(a, b);
    return *(uint32_t*)&t;
}

// ============================================================================
// Device scratch: B^T in bf16 hi/lo, K padded to 1024 (zeros). Bt[n][k]=B[k][n]
// ============================================================================
__device__ __nv_bfloat16 g_Bh[128 * 1024];
__device__ __nv_bfloat16 g_Bl[128 * 1024];

__global__ void __launch_bounds__(256) bconv_kernel(const float* __restrict__ B) {
    int idx = blockIdx.x * 256 + threadIdx.x;   // 131072
    int n = idx >> 10;
    int k = idx & 1023;
    float v = (k < 1000) ? B[k * 128 + n] : 0.f;
    __nv_bfloat16 h = __float2bfloat16(v);
    g_Bh[idx] = h;
    g_Bl[idx] = __float2bfloat16(v - __bfloat162float(h));
}

// ============================================================================
// Kernel B: attr GEMM, warp-level bf16 mma.sync split (C = AhBh + AlBh + AhBl)
// C[8192,128] = A[8192,1000] @ B[1000,128]
// grid=128 (BM=64, BN=128), 256 thr = 8 warps as 2(M) x 4(N), warp tile 32x32.
// ============================================================================
#define GK     1000
#define CH     64
#define NCH    16
#define PITCH  144
#define SA_H   0
#define SA_L   (64 * PITCH)                 //  9216
#define SB_H   (2 * 64 * PITCH)             // 18432
#define SB_L   (SB_H + 128 * PITCH)         // 36864
#define SMEM_GEMM (SB_L + 128 * PITCH)      // 55296

__global__ void __launch_bounds__(256)
attr_gemm_mma(const float* __restrict__ A, float* __restrict__ C) {
    char* smem = dyn_smem;
    const uint32_t sb = s2u(smem);
    const int tid  = threadIdx.x;
    const int wid  = tid >> 5;
    const int lane = tid & 31;
    const int bm   = blockIdx.x * 64;

    const int wm = wid >> 2;              // 0..1  (M 32-tile)
    const int wn = wid & 3;               // 0..3  (N 32-tile)
    const int g  = lane >> 2;             // 0..7  fragment group row
    const int tb = (lane & 3) * 4;        // byte offset of this thread's k-pair

    // staging: A rows (row = tid>>2, 16 k each), B rows (n = tid>>1, 32 k each)
    const int arow = tid >> 2, akseg = tid & 3;
    const int brow = tid >> 1, bseg  = tid & 1;
    const float* aptr = A + (size_t)(bm + arow) * GK;
    const __nv_bfloat16* bhp = g_Bh + brow * 1024 + bseg * 32;
    const __nv_bfloat16* blp = g_Bl + brow * 1024 + bseg * 32;

    float  as[16];
    uint4  bh4[4], bl4[4];   // 32 bf16 each = full half-row of the 64-k chunk

    // prologue: stage chunk 0
    {
        const float4* ap4 = (const float4*)(aptr + akseg * 16);
        #pragma unroll
        for (int i = 0; i < 4; i++) {
            float4 v = ap4[i];
            as[4*i+0] = v.x; as[4*i+1] = v.y; as[4*i+2] = v.z; as[4*i+3] = v.w;
        }
        #pragma unroll
        for (int i = 0; i < 4; i++) {
            bh4[i] = *(const uint4*)(bhp + i * 8);
            bl4[i] = *(const uint4*)(blp + i * 8);
        }
    }

    float acc[2][4][4];
    #pragma unroll
    for (int mt = 0; mt < 2; mt++)
        #pragma unroll
        for (int nt = 0; nt < 4; nt++)
            #pragma unroll
            for (int q = 0; q < 4; q++) acc[mt][nt][q] = 0.f;

    #pragma unroll 1
    for (int c = 0; c < NCH; c++) {
        if (c > 0) __syncthreads();     // previous compute done reading smem

        // ---- store staged chunk: A fp32 -> bf16 hi/lo; B already split ----
        {
            char* pa = smem + SA_H + arow * PITCH + akseg * 32;
            char* pl = smem + SA_L + arow * PITCH + akseg * 32;
            uint4 hv, lv;
            #pragma unroll
            for (int half = 0; half < 2; half++) {
                const float* f = as + half * 8;
                __nv_bfloat16 h0 = __float2bfloat16(f[0]), h1 = __float2bfloat16(f[1]);
                __nv_bfloat16 h2 = __float2bfloat16(f[2]), h3 = __float2bfloat16(f[3]);
                __nv_bfloat16 h4 = __float2bfloat16(f[4]), h5 = __float2bfloat16(f[5]);
                __nv_bfloat16 h6 = __float2bfloat16(f[6]), h7 = __float2bfloat16(f[7]);
                hv.x = pack_bf2(f[0], f[1]); hv.y = pack_bf2(f[2], f[3]);
                hv.z = pack_bf2(f[4], f[5]); hv.w = pack_bf2(f[6], f[7]);
                lv.x = pack_bf2(f[0]-__bfloat162float(h0), f[1]-__bfloat162float(h1));
                lv.y = pack_bf2(f[2]-__bfloat162float(h2), f[3]-__bfloat162float(h3));
                lv.z = pack_bf2(f[4]-__bfloat162float(h4), f[5]-__bfloat162float(h5));
                lv.w = pack_bf2(f[6]-__bfloat162float(h6), f[7]-__bfloat162float(h7));
                *(uint4*)(pa + half * 16) = hv;
                *(uint4*)(pl + half * 16) = lv;
            }
            // B: each thread owns 32 bf16 = 64 bytes at byte offset bseg*64
            char* pbh = smem + SB_H + brow * PITCH + bseg * 64;
            char* pbl = smem + SB_L + brow * PITCH + bseg * 64;
            #pragma unroll
            for (int i = 0; i < 4; i++) {
                *(uint4*)(pbh + i * 16) = bh4[i];
                *(uint4*)(pbl + i * 16) = bl4[i];
            }
        }
        __syncthreads();

        // ---- prefetch next chunk (LDG overlaps mma) ----
        if (c + 1 < NCH) {
            const int k0 = (c + 1) * CH;
            if (c + 1 < NCH - 1) {
                const float4* ap4 = (const float4*)(aptr + k0 + akseg * 16);
                #pragma unroll
                for (int i = 0; i < 4; i++) {
                    float4 v = ap4[i];
                    as[4*i+0]=v.x; as[4*i+1]=v.y; as[4*i+2]=v.z; as[4*i+3]=v.w;
                }
            } else {                      // tail chunk: elementwise guard (K=1000)
                #pragma unroll
                for (int i = 0; i < 16; i++) {
                    int kg = k0 + akseg * 16 + i;
                    as[i] = (kg < GK) ? aptr[kg] : 0.f;
                }
            }
            #pragma unroll
            for (int i = 0; i < 4; i++) {
                bh4[i] = *(const uint4*)(bhp + k0 + i * 8);
                bl4[i] = *(const uint4*)(blp + k0 + i * 8);
            }
        }

        // ---- compute: 4 k16 steps x 3 passes x (2m x 4n) mma ----
        // Direct LDS at documented m16n8k16 fragment coords:
        //   a0=(row g, k 2t), a1=(row g+8), a2=(k+8), a3=(row+8,k+8)
        //   b0=(n g, k 2t),   b1=(k+8)
        #pragma unroll
        for (int ks = 0; ks < 4; ks++) {
            uint32_t ah[2][4], al[2][4], bh[4][2], bl[4][2];
            #pragma unroll
            for (int mt = 0; mt < 2; mt++) {
                uint32_t baseH = sb + SA_H + (uint32_t)((wm*32 + mt*16 + g) * PITCH + ks*32 + tb);
                uint32_t baseL = sb + SA_L + (uint32_t)((wm*32 + mt*16 + g) * PITCH + ks*32 + tb);
                ah[mt][0] = lds32(baseH);
                ah[mt][1] = lds32(baseH + 8 * PITCH);
                ah[mt][2] = lds32(baseH + 16);
                ah[mt][3] = lds32(baseH + 8 * PITCH + 16);
                al[mt][0] = lds32(baseL);
                al[mt][1] = lds32(baseL + 8 * PITCH);
                al[mt][2] = lds32(baseL + 16);
                al[mt][3] = lds32(baseL + 8 * PITCH + 16);
            }
            #pragma unroll
            for (int nt = 0; nt < 4; nt++) {
                uint32_t baseH = sb + SB_H + (uint32_t)((wn*32 + nt*8 + g) * PITCH + ks*32 + tb);
                uint32_t baseL = sb + SB_L + (uint32_t)((wn*32 + nt*8 + g) * PITCH + ks*32 + tb);
                bh[nt][0] = lds32(baseH);
                bh[nt][1] = lds32(baseH + 16);
                bl[nt][0] = lds32(baseL);
                bl[nt][1] = lds32(baseL + 16);
            }
            #pragma unroll
            for (int mt = 0; mt < 2; mt++)
                #pragma unroll
                for (int nt = 0; nt < 4; nt++) {
                    mma16816(acc[mt][nt], ah[mt], bh[nt]);   // Ah*Bh
                    mma16816(acc[mt][nt], al[mt], bh[nt]);   // Al*Bh
                    mma16816(acc[mt][nt], ah[mt], bl[nt]);   // Ah*Bl
                }
        }
    }

    // ---- epilogue: c0=C[g][2t], c1=C[g][2t+1], c2=C[g+8][2t], c3=C[g+8][2t+1]
    const int t = lane & 3;
    #pragma unroll
    for (int mt = 0; mt < 2; mt++)
        #pragma unroll
        for (int nt = 0; nt < 4; nt++) {
            int row0 = bm + wm * 32 + mt * 16 + g;
            int col  = wn * 32 + nt * 8 + t * 2;
            *(float2*)&C[(size_t)row0 * 128 + col] =
                make_float2(acc[mt][nt][0], acc[mt][nt][1]);
            *(float2*)&C[(size_t)(row0 + 8) * 128 + col] =
                make_float2(acc[mt][nt][2], acc[mt][nt][3]);
        }
}

// ============================================================================
// Kernel A: masked edge-type attention + aggregation (unchanged; passing).
// grid=(64,4), block=(128,2). h_s row-major [j][d], stride 132.
// ============================================================================
#define HST 132
__global__ void __launch_bounds__(256) attn_kernel(
    const float* __restrict__ hidden,   // [64,128,128]
    const int*   __restrict__ adj,      // [64,128,128]
    const float* __restrict__ a,        // [128,4]
    float*       __restrict__ out)      // [64,128,128]
{
    float* smem   = (float*)dyn_smem;
    float* h_s    = smem;                 // 128*132
    float* a_t    = h_s + 128 * HST;      // 4*132
    float* attn_s = a_t + 4 * HST;        // 2*128
    float* red    = attn_s + 256;         // 2*4

    const int b   = blockIdx.x;
    const int tx  = threadIdx.x;
    const int ty  = threadIdx.y;
    const int tid = ty * 128 + tx;

    const float4* hb4 = (const float4*)(hidden + b * 16384);
    #pragma unroll 4
    for (int idx = tid; idx < 4096; idx += 256) {
        int j  = idx >> 5;
        int ds = idx & 31;
        *(float4*)&h_s[j * HST + ds * 4] = hb4[idx];
    }
    #pragma unroll
    for (int t = tid; t < 512; t += 256) {
        int k = t & 3, d = t >> 2;
        a_t[k * HST + d] = a[t];
    }
    __syncthreads();

    const int lane = tx & 31;
    const int w    = tx >> 5;

    for (int ii = 0; ii < 16; ++ii) {
        const int i = blockIdx.y * 32 + ii * 2 + ty;

        const int e = adj[(b * 128 + i) * 128 + tx];
        const int k = (e > 0) ? (e - 1) : 0;

        const float4* hi = (const float4*)&h_s[i * HST];
        const float4* hj = (const float4*)&h_s[tx * HST];
        const float4* ar = (const float4*)&a_t[k * HST];

        float accp = 0.f, accn = 0.f;
        #pragma unroll 8
        for (int dd = 0; dd < 32; ++dd) {
            float4 x = hi[dd], y = hj[dd], wv = ar[dd];
            float p;
            p = x.x * y.x; accp = fmaf(fmaxf(p, 0.f), wv.x, accp); accn = fmaf(fminf(p, 0.f), wv.x, accn);
            p = x.y * y.y; accp = fmaf(fmaxf(p, 0.f), wv.y, accp); accn = fmaf(fminf(p, 0.f), wv.y, accn);
            p = x.z * y.z; accp = fmaf(fmaxf(p, 0.f), wv.z, accp); accn = fmaf(fminf(p, 0.f), wv.z, accn);
            p = x.w * y.w; accp = fmaf(fmaxf(p, 0.f), wv.w, accp); accn = fmaf(fminf(p, 0.f), wv.w, accn);
        }
        float alpha = (e != 0) ? fmaf(LRELU_ALPHA, accn, accp) : NEG_INF_F;

        float m = alpha;
        #pragma unroll
        for (int o = 16; o; o >>= 1)
            m = fmaxf(m, __shfl_xor_sync(0xffffffffu, m, o));
        if (lane == 0) red[ty * 4 + w] = m;
        __syncthreads();
        m = fmaxf(fmaxf(red[ty * 4 + 0], red[ty * 4 + 1]),
                  fmaxf(red[ty * 4 + 2], red[ty * 4 + 3]));

        float ex = __expf(alpha - m);
        float s = ex;
        #pragma unroll
        for (int o = 16; o; o >>= 1)
            s += __shfl_xor_sync(0xffffffffu, s, o);
        __syncthreads();
        if (lane == 0) red[ty * 4 + w] = s;
        __syncthreads();
        s = (red[ty * 4 + 0] + red[ty * 4 + 1]) +
            (red[ty * 4 + 2] + red[ty * 4 + 3]);

        attn_s[ty * 128 + tx] = ex * (1.f / s);
        __syncthreads();

        const float4* at = (const float4*)&attn_s[ty * 128];
        float acc2 = 0.f;
        #pragma unroll 8
        for (int j4 = 0; j4 < 32; ++j4) {
            float4 av = at[j4];
            int j = j4 * 4;
            acc2 = fmaf(av.x, h_s[(j + 0) * HST + tx], acc2);
            acc2 = fmaf(av.y, h_s[(j + 1) * HST + tx], acc2);
            acc2 = fmaf(av.z, h_s[(j + 2) * HST + tx], acc2);
            acc2 = fmaf(av.w, h_s[(j + 3) * HST + tx], acc2);
        }
        out[(b * 128 + i) * 128 + tx] = acc2;
        __syncthreads();
    }
}

// ============================================================================
extern "C" void kernel_launch(void* const* d_in, const int* in_sizes, int n_in,
                              void* d_out, int out_size)
{
    const float* hidden   = (const float*)d_in[0];  // [64,128,128]
    const int*   adj      = (const int*)  d_in[1];  // [64,128,128]
    const float* a        = (const float*)d_in[2];  // [128,4]
    const float* A_attr   = (const float*)d_in[3];  // [64,128,1000]
    const float* attr_emb = (const float*)d_in[4];  // [1000,128]

    float* out       = (float*)d_out;
    float* out_attn  = out;                   // output    [64,128,128]
    float* out_attr  = out + 64 * 128 * 128;  // attr_sess [64,128,128]

    size_t attn_smem = (size_t)(128 * HST + 4 * HST + 256 + 8) * sizeof(float);
    cudaFuncSetAttribute(attn_kernel,
                         cudaFuncAttributeMaxDynamicSharedMemorySize, (int)attn_smem);
    cudaFuncSetAttribute(attr_gemm_mma,
                         cudaFuncAttributeMaxDynamicSharedMemorySize, SMEM_GEMM);

    bconv_kernel<<<512, 256>>>(attr_emb);
    attr_gemm_mma<<<128, 256, SMEM_GEMM>>>(A_attr, out_attr);
    attn_kernel<<<dim3(64, 4), dim3(128, 2), attn_smem>>>(hidden, adj, a, out_attn);
}

// round 8
// speedup vs baseline: 1.5899x; 1.0452x over previous
#include <cuda_runtime.h>
#include <cuda_bf16.h>
#include <cstdint>
#include <math.h>

#define NEG_INF_F   (-9.0e15f)
#define LRELU_ALPHA (0.2f)

extern __shared__ char dyn_smem[];

// ============================================================================
// Helpers
// ============================================================================
__device__ __forceinline__ uint32_t s2u(const void* p) {
    uint32_t a;
    asm("{ .reg .u64 t; cvta.to.shared.u64 t, %1; cvt.u32.u64 %0, t; }"
        : "=r"(a) : "l"(p));
    return a;
}
__device__ __forceinline__ void ldm_x4(uint32_t* r, uint32_t addr) {
    asm volatile("ldmatrix.sync.aligned.m8n8.x4.shared.b16 {%0,%1,%2,%3}, [%4];"
                 : "=r"(r[0]), "=r"(r[1]), "=r"(r[2]), "=r"(r[3]) : "r"(addr));
}
__device__ __forceinline__ void mma16816(float* c, const uint32_t* a, const uint32_t* b) {
    asm volatile(
        "mma.sync.aligned.m16n8k16.row.col.f32.bf16.bf16.f32 "
        "{%0,%1,%2,%3}, {%4,%5,%6,%7}, {%8,%9}, {%0,%1,%2,%3};"
        : "+f"(c[0]), "+f"(c[1]), "+f"(c[2]), "+f"(c[3])
        : "r"(a[0]), "r"(a[1]), "r"(a[2]), "r"(a[3]), "r"(b[0]), "r"(b[1]));
}
__device__ __forceinline__ uint32_t pack_bf2(float a, float b) {
    __nv_bfloat162 t = __floats2bfloat162_rn(a, b);
    return *(uint32_t*)&t;
}

// ============================================================================
// Device scratch: B^T in bf16 hi/lo, K padded to 1024 (zeros). Bt[n][k]=B[k][n]
// ============================================================================
__device__ __nv_bfloat16 g_Bh[128 * 1024];
__device__ __nv_bfloat16 g_Bl[128 * 1024];

__global__ void __launch_bounds__(256) bconv_kernel(const float* __restrict__ B) {
    int idx = blockIdx.x * 256 + threadIdx.x;   // 131072
    int n = idx >> 10;
    int k = idx & 1023;
    float v = (k < 1000) ? B[k * 128 + n] : 0.f;
    __nv_bfloat16 h = __float2bfloat16(v);
    g_Bh[idx] = h;
    g_Bl[idx] = __float2bfloat16(v - __bfloat162float(h));
}

// ============================================================================
// Kernel B: attr GEMM, warp-level bf16 mma.sync split (C = AhBh + AlBh + AhBl)
// C[8192,128] = A[8192,1000] @ B[1000,128]
// grid=128 (BM=64, BN=128), 256 thr = 8 warps as 2(M) x 4(N), warp tile 32x32.
// Fragment loads via ldmatrix.x4 (addressing verified; staging carries the data).
// ============================================================================
#define GK     1000
#define CH     64
#define NCH    16
#define PITCH  144
#define SA_H   0
#define SA_L   (64 * PITCH)                 //  9216
#define SB_H   (2 * 64 * PITCH)             // 18432
#define SB_L   (SB_H + 128 * PITCH)         // 36864
#define SMEM_GEMM (SB_L + 128 * PITCH)      // 55296

__global__ void __launch_bounds__(256)
attr_gemm_mma(const float* __restrict__ A, float* __restrict__ C) {
    char* smem = dyn_smem;
    const uint32_t sb = s2u(smem);
    const int tid  = threadIdx.x;
    const int wid  = tid >> 5;
    const int lane = tid & 31;
    const int bm   = blockIdx.x * 64;

    const int wm = wid >> 2;              // 0..1  (M 32-tile)
    const int wn = wid & 3;               // 0..3  (N 32-tile)

    // ldmatrix lane->address maps (within a 16-row x 32-byte k-slab):
    //  A tile: lanes 0-15 -> rows 0-15 @ +0B ; lanes 16-31 -> rows 0-15 @ +16B
    //    => {r0,r1,r2,r3} = {(m0-7,k0-7),(m8-15,k0-7),(m0-7,k8-15),(m8-15,k8-15)} = a-frag order
    //  B tile: lanes 0-7 rows0-7 @0 ; 8-15 rows0-7 @16 ; 16-23 rows8-15 @0 ; 24-31 rows8-15 @16
    //    => {r0,r1} = b-frag (n0-7), {r2,r3} = b-frag (n8-15)
    const uint32_t aOff = (uint32_t)((lane & 15) * PITCH + (lane >> 4) * 16);
    const uint32_t bOff = (uint32_t)(((((lane >> 4) & 1) << 3) + (lane & 7)) * PITCH
                                     + ((lane >> 3) & 1) * 16);

    // staging: A rows (row = tid>>2, 16 k each), B rows (n = tid>>1, 32 k each)
    const int arow = tid >> 2, akseg = tid & 3;
    const int brow = tid >> 1, bseg  = tid & 1;
    const float* aptr = A + (size_t)(bm + arow) * GK;
    const __nv_bfloat16* bhp = g_Bh + brow * 1024 + bseg * 32;
    const __nv_bfloat16* blp = g_Bl + brow * 1024 + bseg * 32;

    float  as[16];
    uint4  bh4[4], bl4[4];   // 32 bf16 each = full half-row of the 64-k chunk

    // prologue: stage chunk 0
    {
        const float4* ap4 = (const float4*)(aptr + akseg * 16);
        #pragma unroll
        for (int i = 0; i < 4; i++) {
            float4 v = ap4[i];
            as[4*i+0] = v.x; as[4*i+1] = v.y; as[4*i+2] = v.z; as[4*i+3] = v.w;
        }
        #pragma unroll
        for (int i = 0; i < 4; i++) {
            bh4[i] = *(const uint4*)(bhp + i * 8);
            bl4[i] = *(const uint4*)(blp + i * 8);
        }
    }

    float acc[2][4][4];
    #pragma unroll
    for (int mt = 0; mt < 2; mt++)
        #pragma unroll
        for (int nt = 0; nt < 4; nt++)
            #pragma unroll
            for (int q = 0; q < 4; q++) acc[mt][nt][q] = 0.f;

    #pragma unroll 1
    for (int c = 0; c < NCH; c++) {
        if (c > 0) __syncthreads();     // previous compute done reading smem

        // ---- store staged chunk: A fp32 -> bf16 hi/lo; B already split ----
        {
            char* pa = smem + SA_H + arow * PITCH + akseg * 32;
            char* pl = smem + SA_L + arow * PITCH + akseg * 32;
            uint4 hv, lv;
            #pragma unroll
            for (int half = 0; half < 2; half++) {
                const float* f = as + half * 8;
                __nv_bfloat16 h0 = __float2bfloat16(f[0]), h1 = __float2bfloat16(f[1]);
                __nv_bfloat16 h2 = __float2bfloat16(f[2]), h3 = __float2bfloat16(f[3]);
                __nv_bfloat16 h4 = __float2bfloat16(f[4]), h5 = __float2bfloat16(f[5]);
                __nv_bfloat16 h6 = __float2bfloat16(f[6]), h7 = __float2bfloat16(f[7]);
                hv.x = pack_bf2(f[0], f[1]); hv.y = pack_bf2(f[2], f[3]);
                hv.z = pack_bf2(f[4], f[5]); hv.w = pack_bf2(f[6], f[7]);
                lv.x = pack_bf2(f[0]-__bfloat162float(h0), f[1]-__bfloat162float(h1));
                lv.y = pack_bf2(f[2]-__bfloat162float(h2), f[3]-__bfloat162float(h3));
                lv.z = pack_bf2(f[4]-__bfloat162float(h4), f[5]-__bfloat162float(h5));
                lv.w = pack_bf2(f[6]-__bfloat162float(h6), f[7]-__bfloat162float(h7));
                *(uint4*)(pa + half * 16) = hv;
                *(uint4*)(pl + half * 16) = lv;
            }
            // B: each thread owns 32 bf16 = 64 bytes at byte offset bseg*64
            char* pbh = smem + SB_H + brow * PITCH + bseg * 64;
            char* pbl = smem + SB_L + brow * PITCH + bseg * 64;
            #pragma unroll
            for (int i = 0; i < 4; i++) {
                *(uint4*)(pbh + i * 16) = bh4[i];
                *(uint4*)(pbl + i * 16) = bl4[i];
            }
        }
        __syncthreads();

        // ---- prefetch next chunk (LDG overlaps mma) ----
        if (c + 1 < NCH) {
            const int k0 = (c + 1) * CH;
            if (c + 1 < NCH - 1) {
                const float4* ap4 = (const float4*)(aptr + k0 + akseg * 16);
                #pragma unroll
                for (int i = 0; i < 4; i++) {
                    float4 v = ap4[i];
                    as[4*i+0]=v.x; as[4*i+1]=v.y; as[4*i+2]=v.z; as[4*i+3]=v.w;
                }
            } else {                      // tail chunk: elementwise guard (K=1000)
                #pragma unroll
                for (int i = 0; i < 16; i++) {
                    int kg = k0 + akseg * 16 + i;
                    as[i] = (kg < GK) ? aptr[kg] : 0.f;
                }
            }
            #pragma unroll
            for (int i = 0; i < 4; i++) {
                bh4[i] = *(const uint4*)(bhp + k0 + i * 8);
                bl4[i] = *(const uint4*)(blp + k0 + i * 8);
            }
        }

        // ---- compute: 4 k16 steps x 3 passes x (2m x 4n) mma ----
        const uint32_t aBaseH = sb + SA_H + (uint32_t)(wm * 32 * PITCH) + aOff;
        const uint32_t aBaseL = sb + SA_L + (uint32_t)(wm * 32 * PITCH) + aOff;
        const uint32_t bBaseH = sb + SB_H + (uint32_t)(wn * 32 * PITCH) + bOff;
        const uint32_t bBaseL = sb + SB_L + (uint32_t)(wn * 32 * PITCH) + bOff;

        #pragma unroll
        for (int ks = 0; ks < 4; ks++) {
            uint32_t ah[2][4], al[2][4], bhv[2][4], blv[2][4];
            #pragma unroll
            for (int mt = 0; mt < 2; mt++) {
                ldm_x4(ah[mt], aBaseH + mt * 16 * PITCH + ks * 32);
                ldm_x4(al[mt], aBaseL + mt * 16 * PITCH + ks * 32);
            }
            #pragma unroll
            for (int nh = 0; nh < 2; nh++) {
                ldm_x4(bhv[nh], bBaseH + nh * 16 * PITCH + ks * 32);
                ldm_x4(blv[nh], bBaseL + nh * 16 * PITCH + ks * 32);
            }
            #pragma unroll
            for (int mt = 0; mt < 2; mt++)
                #pragma unroll
                for (int nt = 0; nt < 4; nt++) {
                    const uint32_t* bhreg = &bhv[nt >> 1][(nt & 1) * 2];
                    const uint32_t* blreg = &blv[nt >> 1][(nt & 1) * 2];
                    mma16816(acc[mt][nt], ah[mt], bhreg);   // Ah*Bh
                    mma16816(acc[mt][nt], al[mt], bhreg);   // Al*Bh
                    mma16816(acc[mt][nt], ah[mt], blreg);   // Ah*Bl
                }
        }
    }

    // ---- epilogue: c0=C[g][2t], c1=C[g][2t+1], c2=C[g+8][2t], c3=C[g+8][2t+1]
    const int g = lane >> 2, t = lane & 3;
    #pragma unroll
    for (int mt = 0; mt < 2; mt++)
        #pragma unroll
        for (int nt = 0; nt < 4; nt++) {
            int row0 = bm + wm * 32 + mt * 16 + g;
            int col  = wn * 32 + nt * 8 + t * 2;
            *(float2*)&C[(size_t)row0 * 128 + col] =
                make_float2(acc[mt][nt][0], acc[mt][nt][1]);
            *(float2*)&C[(size_t)(row0 + 8) * 128 + col] =
                make_float2(acc[mt][nt][2], acc[mt][nt][3]);
        }
}

// ============================================================================
// Kernel A: masked edge-type attention + aggregation.
// lrelu identity: sum lrelu(p)*a = 0.2*sum(p*a) + 0.8*sum(max(p,0)*a)
// -> 4 ops/d inner loop (mul, fma, max, fma).
// grid=(64,4), block=(128,2). h_s row-major [j][d], stride 132.
// ============================================================================
#define HST 132
__global__ void __launch_bounds__(256) attn_kernel(
    const float* __restrict__ hidden,   // [64,128,128]
    const int*   __restrict__ adj,      // [64,128,128]
    const float* __restrict__ a,        // [128,4]
    float*       __restrict__ out)      // [64,128,128]
{
    float* smem   = (float*)dyn_smem;
    float* h_s    = smem;                 // 128*132
    float* a_t    = h_s + 128 * HST;      // 4*132
    float* attn_s = a_t + 4 * HST;        // 2*128
    float* red    = attn_s + 256;         // 2*4

    const int b   = blockIdx.x;
    const int tx  = threadIdx.x;
    const int ty  = threadIdx.y;
    const int tid = ty * 128 + tx;

    const float4* hb4 = (const float4*)(hidden + b * 16384);
    #pragma unroll 4
    for (int idx = tid; idx < 4096; idx += 256) {
        int j  = idx >> 5;
        int ds = idx & 31;
        *(float4*)&h_s[j * HST + ds * 4] = hb4[idx];
    }
    #pragma unroll
    for (int t = tid; t < 512; t += 256) {
        int k = t & 3, d = t >> 2;
        a_t[k * HST + d] = a[t];
    }
    __syncthreads();

    const int lane = tx & 31;
    const int w    = tx >> 5;

    for (int ii = 0; ii < 16; ++ii) {
        const int i = blockIdx.y * 32 + ii * 2 + ty;

        const int e = adj[(b * 128 + i) * 128 + tx];
        const int k = (e > 0) ? (e - 1) : 0;

        const float4* hi = (const float4*)&h_s[i * HST];
        const float4* hj = (const float4*)&h_s[tx * HST];
        const float4* ar = (const float4*)&a_t[k * HST];

        float accA = 0.f, accB = 0.f;   // accA = sum p*a ; accB = sum max(p,0)*a
        #pragma unroll 8
        for (int dd = 0; dd < 32; ++dd) {
            float4 x = hi[dd], y = hj[dd], wv = ar[dd];
            float p;
            p = x.x * y.x; accA = fmaf(p, wv.x, accA); accB = fmaf(fmaxf(p, 0.f), wv.x, accB);
            p = x.y * y.y; accA = fmaf(p, wv.y, accA); accB = fmaf(fmaxf(p, 0.f), wv.y, accB);
            p = x.z * y.z; accA = fmaf(p, wv.z, accA); accB = fmaf(fmaxf(p, 0.f), wv.z, accB);
            p = x.w * y.w; accA = fmaf(p, wv.w, accA); accB = fmaf(fmaxf(p, 0.f), wv.w, accB);
        }
        float alpha = (e != 0)
            ? fmaf(LRELU_ALPHA, accA, (1.f - LRELU_ALPHA) * accB)
            : NEG_INF_F;

        float m = alpha;
        #pragma unroll
        for (int o = 16; o; o >>= 1)
            m = fmaxf(m, __shfl_xor_sync(0xffffffffu, m, o));
        if (lane == 0) red[ty * 4 + w] = m;
        __syncthreads();
        m = fmaxf(fmaxf(red[ty * 4 + 0], red[ty * 4 + 1]),
                  fmaxf(red[ty * 4 + 2], red[ty * 4 + 3]));

        float ex = __expf(alpha - m);
        float s = ex;
        #pragma unroll
        for (int o = 16; o; o >>= 1)
            s += __shfl_xor_sync(0xffffffffu, s, o);
        __syncthreads();
        if (lane == 0) red[ty * 4 + w] = s;
        __syncthreads();
        s = (red[ty * 4 + 0] + red[ty * 4 + 1]) +
            (red[ty * 4 + 2] + red[ty * 4 + 3]);

        attn_s[ty * 128 + tx] = ex * (1.f / s);
        __syncthreads();

        const float4* at = (const float4*)&attn_s[ty * 128];
        float acc2 = 0.f;
        #pragma unroll 8
        for (int j4 = 0; j4 < 32; ++j4) {
            float4 av = at[j4];
            int j = j4 * 4;
            acc2 = fmaf(av.x, h_s[(j + 0) * HST + tx], acc2);
            acc2 = fmaf(av.y, h_s[(j + 1) * HST + tx], acc2);
            acc2 = fmaf(av.z, h_s[(j + 2) * HST + tx], acc2);
            acc2 = fmaf(av.w, h_s[(j + 3) * HST + tx], acc2);
        }
        out[(b * 128 + i) * 128 + tx] = acc2;
        __syncthreads();
    }
}

// ============================================================================
extern "C" void kernel_launch(void* const* d_in, const int* in_sizes, int n_in,
                              void* d_out, int out_size)
{
    const float* hidden   = (const float*)d_in[0];  // [64,128,128]
    const int*   adj      = (const int*)  d_in[1];  // [64,128,128]
    const float* a        = (const float*)d_in[2];  // [128,4]
    const float* A_attr   = (const float*)d_in[3];  // [64,128,1000]
    const float* attr_emb = (const float*)d_in[4];  // [1000,128]

    float* out       = (float*)d_out;
    float* out_attn  = out;                   // output    [64,128,128]
    float* out_attr  = out + 64 * 128 * 128;  // attr_sess [64,128,128]

    size_t attn_smem = (size_t)(128 * HST + 4 * HST + 256 + 8) * sizeof(float);
    cudaFuncSetAttribute(attn_kernel,
                         cudaFuncAttributeMaxDynamicSharedMemorySize, (int)attn_smem);
    cudaFuncSetAttribute(attr_gemm_mma,
                         cudaFuncAttributeMaxDynamicSharedMemorySize, SMEM_GEMM);

    bconv_kernel<<<512, 256>>>(attr_emb);
    attr_gemm_mma<<<128, 256, SMEM_GEMM>>>(A_attr, out_attr);
    attn_kernel<<<dim3(64, 4), dim3(128, 2), attn_smem>>>(hidden, adj, a, out_attn);
}